// round 1
// baseline (speedup 1.0000x reference)
#include <cuda_runtime.h>
#include <cuda_fp16.h>
#include <cstdint>
#include <cstddef>

#define BATCH 4
#define NDIM  4096
#define CDIM  256
#define NHOP  3

// ---------------- static device scratch (no allocations allowed) ----------------
__device__ float  g_bhA [(size_t)BATCH * NDIM * NDIM];   // bh fp32 (ping)   256MB
__device__ float  g_bhB [(size_t)BATCH * NDIM * NDIM];   // bh fp32 (pong)   256MB
__device__ __half g_bhhA[(size_t)BATCH * NDIM * NDIM];   // bh fp16 (ping)   128MB
__device__ __half g_bhhB[(size_t)BATCH * NDIM * NDIM];   // bh fp16 (pong)   128MB
__device__ __half g_b0t [(size_t)BATCH * NDIM * NDIM];   // b0^T fp16        128MB
__device__ __half g_P   [(size_t)BATCH * NDIM * NDIM];   // softmax probs    128MB
__device__ __half g_M   [(size_t)BATCH * CDIM * NDIM];   // conv@nodes fp16    8MB

// ---------------- binarize + transpose ----------------
// b0 = (sigmoid(W) - delta >= 0); writes fp32 bh ping, fp16 bh ping, fp16 b0^T
__global__ __launch_bounds__(256) void binarize_kernel(const float* __restrict__ W,
                                                       const float* __restrict__ delta_p)
{
    __shared__ __half tile[32][33];
    const float delta = delta_p[0];
    const int b  = blockIdx.z;
    const int i0 = blockIdx.y << 5;
    const int j0 = blockIdx.x << 5;
    const size_t base = (size_t)b * NDIM * NDIM;
    const int tx = threadIdx.x, ty = threadIdx.y;   // 32 x 8

#pragma unroll
    for (int p = 0; p < 4; p++) {
        const int i = i0 + ty + p * 8;
        const size_t idx = base + (size_t)i * NDIM + (j0 + tx);
        float w  = W[idx];
        float sg = 1.0f / (1.0f + expf(-w));
        float v  = (sg - delta >= 0.0f) ? 1.0f : 0.0f;
        g_bhA[idx]  = v;
        g_bhhA[idx] = __float2half_rn(v);
        tile[ty + p * 8][tx] = __float2half_rn(v);
    }
    __syncthreads();
#pragma unroll
    for (int p = 0; p < 4; p++) {
        const int jj = ty + p * 8;
        g_b0t[base + (size_t)(j0 + jj) * NDIM + (i0 + tx)] = tile[tx][jj];
    }
}

// ---------------- row softmax: P = softmax(bh * W) (fp16 out) ----------------
__global__ __launch_bounds__(256) void softmax_kernel(const float* __restrict__ bh,
                                                      const float* __restrict__ W,
                                                      __half* __restrict__ P)
{
    const size_t row = blockIdx.x;
    const float4* b4 = reinterpret_cast<const float4*>(bh + row * NDIM);
    const float4* w4 = reinterpret_cast<const float4*>(W  + row * NDIM);
    const int t = threadIdx.x;

    float s[16];
#pragma unroll
    for (int q = 0; q < 4; q++) {
        float4 bb = b4[t * 4 + q];
        float4 ww = w4[t * 4 + q];
        s[q * 4 + 0] = bb.x * ww.x;
        s[q * 4 + 1] = bb.y * ww.y;
        s[q * 4 + 2] = bb.z * ww.z;
        s[q * 4 + 3] = bb.w * ww.w;
    }

    float m = s[0];
#pragma unroll
    for (int k = 1; k < 16; k++) m = fmaxf(m, s[k]);

    __shared__ float red[8];
#pragma unroll
    for (int off = 16; off; off >>= 1) m = fmaxf(m, __shfl_xor_sync(0xffffffffu, m, off));
    if ((t & 31) == 0) red[t >> 5] = m;
    __syncthreads();
    m = red[0];
#pragma unroll
    for (int k = 1; k < 8; k++) m = fmaxf(m, red[k]);
    __syncthreads();

    float sum = 0.0f;
#pragma unroll
    for (int k = 0; k < 16; k++) { s[k] = __expf(s[k] - m); sum += s[k]; }
#pragma unroll
    for (int off = 16; off; off >>= 1) sum += __shfl_xor_sync(0xffffffffu, sum, off);
    if ((t & 31) == 0) red[t >> 5] = sum;
    __syncthreads();
    float tot = 0.0f;
#pragma unroll
    for (int k = 0; k < 8; k++) tot += red[k];
    const float inv = 1.0f / tot;

    uint4* P4 = reinterpret_cast<uint4*>((__half*)P + row * NDIM);
#pragma unroll
    for (int g = 0; g < 2; g++) {
        union { uint4 u; __half2 h[4]; } pk;
#pragma unroll
        for (int q = 0; q < 4; q++) {
            int e = g * 8 + q * 2;
            pk.h[q] = __floats2half2_rn(s[e] * inv, s[e + 1] * inv);
        }
        P4[t * 2 + g] = pk.u;
    }
}

// ---------------- M = conv_w[hop] @ nodes[b]  (fp32 SIMT, fp16 out) ----------------
__global__ __launch_bounds__(256) void convmix_kernel(const float* __restrict__ nodes,
                                                      const float* __restrict__ cw)
{
    __shared__ float scw[32][CDIM];    // 32KB
    const int b  = blockIdx.z;
    const int o0 = blockIdx.y * 32;
    const int i0 = blockIdx.x * 512;
    const int t  = threadIdx.x;

    for (int idx = t; idx < 32 * CDIM; idx += 256)
        scw[idx >> 8][idx & 255] = cw[(o0 + (idx >> 8)) * CDIM + (idx & 255)];
    __syncthreads();

    const int i1 = i0 + t, i2 = i0 + 256 + t;
    float acc1[32], acc2[32];
#pragma unroll
    for (int oo = 0; oo < 32; oo++) { acc1[oo] = 0.f; acc2[oo] = 0.f; }

    const float* np = nodes + (size_t)b * CDIM * NDIM;
#pragma unroll 4
    for (int c = 0; c < CDIM; c++) {
        float n1 = np[(size_t)c * NDIM + i1];
        float n2 = np[(size_t)c * NDIM + i2];
#pragma unroll
        for (int oo = 0; oo < 32; oo++) {
            float w = scw[oo][c];
            acc1[oo] += w * n1;
            acc2[oo] += w * n2;
        }
    }
    __half* mp = g_M + (size_t)b * CDIM * NDIM;
#pragma unroll
    for (int oo = 0; oo < 32; oo++) {
        mp[(size_t)(o0 + oo) * NDIM + i1] = __float2half_rn(acc1[oo]);
        mp[(size_t)(o0 + oo) * NDIM + i2] = __float2half_rn(acc2[oo]);
    }
}

// ---------------- fp16 NT GEMM (A[M,K] row-major, B[N,K] row-major) fp32 accum ----------------
__device__ __forceinline__ void ldsm4(uint32_t& r0, uint32_t& r1, uint32_t& r2, uint32_t& r3,
                                      const void* p)
{
    uint32_t addr = (uint32_t)__cvta_generic_to_shared(p);
    asm volatile("ldmatrix.sync.aligned.m8n8.x4.shared.b16 {%0,%1,%2,%3}, [%4];\n"
                 : "=r"(r0), "=r"(r1), "=r"(r2), "=r"(r3) : "r"(addr));
}

__device__ __forceinline__ void mma16816(float* d, const uint32_t* a, uint32_t b0, uint32_t b1)
{
    asm volatile("mma.sync.aligned.m16n8k16.row.col.f32.f16.f16.f32 "
                 "{%0,%1,%2,%3}, {%4,%5,%6,%7}, {%8,%9}, {%0,%1,%2,%3};\n"
                 : "+f"(d[0]), "+f"(d[1]), "+f"(d[2]), "+f"(d[3])
                 : "r"(a[0]), "r"(a[1]), "r"(a[2]), "r"(a[3]), "r"(b0), "r"(b1));
}

__global__ __launch_bounds__(256, 2) void gemm_nt(const __half* __restrict__ A,
                                                  const __half* __restrict__ B,
                                                  float*  __restrict__ Cf,
                                                  __half* __restrict__ Ch,
                                                  const float* __restrict__ bias,
                                                  int M, int Nn, int K,
                                                  size_t sA, size_t sB, size_t sC)
{
    __shared__ __half As[128][40];
    __shared__ __half Bs[128][40];

    const int bz = blockIdx.z;
    A += (size_t)bz * sA;
    B += (size_t)bz * sB;
    const size_t cbase = (size_t)bz * sC;

    const int tid  = threadIdx.x;
    const int warp = tid >> 5, lane = tid & 31;
    const int wm = warp & 3, wn = warp >> 2;
    const int brow = blockIdx.y * 128, bcol = blockIdx.x * 128;

    float acc[2][8][4];
#pragma unroll
    for (int a = 0; a < 2; a++)
#pragma unroll
        for (int b = 0; b < 8; b++)
#pragma unroll
            for (int c = 0; c < 4; c++) acc[a][b][c] = 0.f;

    const int nk = K >> 5;
    const int lr = tid >> 2;          // 0..63
    const int lc = (tid & 3) * 8;     // half-col within 32-wide tile

    int4 ra[2], rb[2];
    // prologue: tile 0
#pragma unroll
    for (int p = 0; p < 2; p++) {
        ra[p] = *reinterpret_cast<const int4*>(A + (size_t)(brow + p * 64 + lr) * K + lc);
        rb[p] = *reinterpret_cast<const int4*>(B + (size_t)(bcol + p * 64 + lr) * K + lc);
    }
#pragma unroll
    for (int p = 0; p < 2; p++) {
        *reinterpret_cast<int4*>(&As[p * 64 + lr][lc]) = ra[p];
        *reinterpret_cast<int4*>(&Bs[p * 64 + lr][lc]) = rb[p];
    }
    __syncthreads();

    for (int kt = 0; kt < nk; kt++) {
        if (kt + 1 < nk) {
            const int kk = (kt + 1) * 32;
#pragma unroll
            for (int p = 0; p < 2; p++) {
                ra[p] = *reinterpret_cast<const int4*>(A + (size_t)(brow + p * 64 + lr) * K + kk + lc);
                rb[p] = *reinterpret_cast<const int4*>(B + (size_t)(bcol + p * 64 + lr) * K + kk + lc);
            }
        }
#pragma unroll
        for (int ks = 0; ks < 2; ks++) {
            uint32_t afr[2][4];
#pragma unroll
            for (int mi = 0; mi < 2; mi++)
                ldsm4(afr[mi][0], afr[mi][1], afr[mi][2], afr[mi][3],
                      &As[wm * 32 + mi * 16 + (lane & 15)][ks * 16 + ((lane >> 4) << 3)]);
            uint32_t bfr[4][4];
#pragma unroll
            for (int nb = 0; nb < 4; nb++)
                ldsm4(bfr[nb][0], bfr[nb][1], bfr[nb][2], bfr[nb][3],
                      &Bs[wn * 64 + nb * 16 + (lane & 15)][ks * 16 + ((lane >> 4) << 3)]);
#pragma unroll
            for (int mi = 0; mi < 2; mi++)
#pragma unroll
                for (int nb = 0; nb < 4; nb++) {
                    mma16816(acc[mi][nb * 2 + 0], afr[mi], bfr[nb][0], bfr[nb][2]);
                    mma16816(acc[mi][nb * 2 + 1], afr[mi], bfr[nb][1], bfr[nb][3]);
                }
        }
        if (kt + 1 < nk) {
            __syncthreads();
#pragma unroll
            for (int p = 0; p < 2; p++) {
                *reinterpret_cast<int4*>(&As[p * 64 + lr][lc]) = ra[p];
                *reinterpret_cast<int4*>(&Bs[p * 64 + lr][lc]) = rb[p];
            }
            __syncthreads();
        }
    }

    // epilogue
    const int g = lane >> 2, tq = lane & 3;
#pragma unroll
    for (int mi = 0; mi < 2; mi++) {
        const int row_a = brow + wm * 32 + mi * 16 + g;
        const int row_b = row_a + 8;
        const float bva = bias ? bias[row_a] : 0.f;
        const float bvb = bias ? bias[row_b] : 0.f;
#pragma unroll
        for (int ni = 0; ni < 8; ni++) {
            const int col = bcol + wn * 64 + ni * 8 + tq * 2;
            float v0 = acc[mi][ni][0] + bva;
            float v1 = acc[mi][ni][1] + bva;
            float v2 = acc[mi][ni][2] + bvb;
            float v3 = acc[mi][ni][3] + bvb;
            *reinterpret_cast<float2*>(Cf + cbase + (size_t)row_a * Nn + col) = make_float2(v0, v1);
            *reinterpret_cast<float2*>(Cf + cbase + (size_t)row_b * Nn + col) = make_float2(v2, v3);
            if (Ch) {
                *reinterpret_cast<__half2*>(Ch + cbase + (size_t)row_a * Nn + col) = __floats2half2_rn(v0, v1);
                *reinterpret_cast<__half2*>(Ch + cbase + (size_t)row_b * Nn + col) = __floats2half2_rn(v2, v3);
            }
        }
    }
}

// ---------------- launch ----------------
extern "C" void kernel_launch(void* const* d_in, const int* in_sizes, int n_in,
                              void* d_out, int out_size)
{
    const float* W      = (const float*)d_in[0];
    const float* nodes  = (const float*)d_in[1];
    const float* delta  = (const float*)d_in[2];
    const float* conv_w = (const float*)d_in[3];
    const float* conv_b = (const float*)d_in[4];
    float* out = (float*)d_out;

    float *bhA, *bhB;
    __half *bhhA, *bhhB, *b0t, *P;
    cudaGetSymbolAddress((void**)&bhA,  g_bhA);
    cudaGetSymbolAddress((void**)&bhB,  g_bhB);
    cudaGetSymbolAddress((void**)&bhhA, g_bhhA);
    cudaGetSymbolAddress((void**)&bhhB, g_bhhB);
    cudaGetSymbolAddress((void**)&b0t,  g_b0t);
    cudaGetSymbolAddress((void**)&P,    g_P);
    __half* Mh;
    cudaGetSymbolAddress((void**)&Mh,   g_M);

    const size_t matS = (size_t)NDIM * NDIM;
    const size_t mS   = (size_t)CDIM * NDIM;

    binarize_kernel<<<dim3(128, 128, BATCH), dim3(32, 8)>>>(W, delta);

    for (int hop = 0; hop < NHOP; hop++) {
        const float* bh = (hop == 1) ? bhB : bhA;   // hop0:A  hop1:B  hop2:A

        convmix_kernel<<<dim3(8, 8, BATCH), 256>>>(nodes, conv_w + hop * CDIM * CDIM);
        softmax_kernel<<<BATCH * NDIM, 256>>>(bh, W, P);
        gemm_nt<<<dim3(32, 2, BATCH), 256>>>(Mh, P,
                                             out + (size_t)hop * BATCH * CDIM * NDIM, (/*Ch*/__half*)nullptr,
                                             conv_b + hop * CDIM,
                                             CDIM, NDIM, NDIM, mS, matS, mS);
        if (hop == 0)
            gemm_nt<<<dim3(32, 32, BATCH), 256>>>(bhhA, b0t, bhB, bhhB, nullptr,
                                                  NDIM, NDIM, NDIM, matS, matS, matS);
        else if (hop == 1)
            gemm_nt<<<dim3(32, 32, BATCH), 256>>>(bhhB, b0t, bhA, (/*Ch*/__half*)nullptr, nullptr,
                                                  NDIM, NDIM, NDIM, matS, matS, matS);
    }
}